// round 4
// baseline (speedup 1.0000x reference)
#include <cuda_runtime.h>

static constexpr long kQSize = 256L * 128 * 512;        // 16,777,216
static constexpr long kAttn  = 8L * 256 * 128 * 256;    // 67,108,864

__device__ float g_lnL[kQSize];
__device__ float g_lnR[kQSize];
__device__ float g_q[kQSize];          // [w][n][c], pre-scaled by 0.125
__device__ float g_kv[2 * kQSize];     // [w][n][k(0:512)|v(512:1024)]
__device__ float g_posp[511 * 1024];   // [p][q_r*0.125 (0:512) | k_r (512:1024)]
__device__ float g_vo[kQSize];         // [w][n][c]
__device__ float g_A12[kAttn];         // [e][w][n][v]  scores -> probs
__device__ float g_T3[kAttn];          // [e][v][w][n]

__device__ __forceinline__ float4 ld4(const float* p) {
  return *reinterpret_cast<const float4*>(p);
}
__device__ __forceinline__ unsigned f2tf(float x) {
  unsigned r;
  asm("cvt.rna.tf32.f32 %0, %1;" : "=r"(r) : "f"(x));
  return r;
}
__device__ __forceinline__ void mma8(float (&d)[4], const unsigned (&a)[4],
                                     const unsigned (&b)[2]) {
  asm("mma.sync.aligned.m16n8k8.row.col.f32.tf32.tf32.f32 "
      "{%0,%1,%2,%3}, {%4,%5,%6,%7}, {%8,%9}, {%0,%1,%2,%3};"
      : "+f"(d[0]), "+f"(d[1]), "+f"(d[2]), "+f"(d[3])
      : "r"(a[0]), "r"(a[1]), "r"(a[2]), "r"(a[3]), "r"(b[0]), "r"(b[1]));
}

// ---------------- LayerNorm: one block per 512-float row ----------------
__global__ void __launch_bounds__(128) ln_kernel(const float* __restrict__ fl,
                                                 const float* __restrict__ fr,
                                                 const float* __restrict__ lw,
                                                 const float* __restrict__ lb) {
  long row = blockIdx.x;
  const float* src;
  float* dst;
  if (row < 32768) { src = fl + row * 512;           dst = g_lnL + row * 512; }
  else             { src = fr + (row - 32768) * 512; dst = g_lnR + (row - 32768) * 512; }
  int t = threadIdx.x;
  float4 x = ld4(src + t * 4);
  float s  = x.x + x.y + x.z + x.w;
  float q2 = x.x * x.x + x.y * x.y + x.z * x.z + x.w * x.w;
#pragma unroll
  for (int o = 16; o > 0; o >>= 1) {
    s  += __shfl_xor_sync(0xffffffffu, s, o);
    q2 += __shfl_xor_sync(0xffffffffu, q2, o);
  }
  __shared__ float ss[4], sq[4];
  if ((t & 31) == 0) { ss[t >> 5] = s; sq[t >> 5] = q2; }
  __syncthreads();
  s  = ss[0] + ss[1] + ss[2] + ss[3];
  q2 = sq[0] + sq[1] + sq[2] + sq[3];
  float mean = s * (1.f / 512.f);
  float var  = q2 * (1.f / 512.f) - mean * mean;
  float rstd = rsqrtf(var + 1e-5f);
  float4 wv = ld4(lw + t * 4), bv = ld4(lb + t * 4);
  float4 o;
  o.x = (x.x - mean) * rstd * wv.x + bv.x;
  o.y = (x.y - mean) * rstd * wv.y + bv.y;
  o.z = (x.z - mean) * rstd * wv.z + bv.z;
  o.w = (x.w - mean) * rstd * wv.w + bv.w;
  *reinterpret_cast<float4*>(dst + t * 4) = o;
}

// ---------------- Tensor-core tf32 GEMM, double-buffered pipeline ----------------
// 0: q = lnL@Wq^T (+b)*0.125 -> g_q         1: kv = lnR@Wkv^T + b -> g_kv
// 2: posp = pos@W[:1024]^T + b (cols<512 *0.125), M=511 guarded -> g_posp
// 3: T1 per (n,e): q.k^T -> A12             4: T2 per (e,w): q.kr^T += A12 (gather B)
// 5: T3 per (e,v): qr.k^T -> T3 (gather A)  6: AV per (n,e): P@V (NN) -> g_vo
// 7: out = vo@Wo^T + b + resid -> d_out
template <int MODE, int BM, int BN>
__global__ void __launch_bounds__(256)
gemm_k(const float* __restrict__ pA, const float* __restrict__ pB,
       const float* __restrict__ pbias, const float* __restrict__ presid,
       const int* __restrict__ pidx, float* __restrict__ pC) {
  constexpr int WGN = BN / 32;       // warps along n
  constexpr int WGM = 8 / WGN;       // warps along m
  constexpr int WM  = BM / WGM;      // rows per warp
  constexpr int MT  = WM / 16;       // 16-row mma tiles per warp
  constexpr int ASZ = BM * 20;
  constexpr int BSZ = (MODE == 6) ? 16 * 136 : BN * 20;
  constexpr int NA  = (BM * 16) / 1024;   // float4 loads per thread (A)
  constexpr int NB  = (BN * 16) / 1024;   // float4 loads per thread (B)
  __shared__ __align__(16) unsigned As[2 * ASZ];
  __shared__ __align__(16) unsigned Bs[2 * BSZ];

  const int tid   = threadIdx.x;
  const int warp  = tid >> 5;
  const int lane  = tid & 31;
  const int gid   = lane >> 2;
  const int tg    = lane & 3;
  const int wm0   = (warp / WGN) * WM;
  const int wn0   = (warp % WGN) * 32;
  const int i0 = blockIdx.y * BM;
  const int j0 = blockIdx.x * BN;
  const int z  = blockIdx.z;

  const float* A = nullptr;
  const float* B = nullptr;
  float* C = nullptr;
  long lda = 0, ldb = 0, ldc = 0;
  int K = 0, e = 0, bb = 0;

  if constexpr (MODE == 0) { A = g_lnL; lda = 512; K = 512; B = pB; ldb = 512; C = g_q; ldc = 512; }
  else if constexpr (MODE == 1) { A = g_lnR; lda = 512; K = 512; B = pB; ldb = 512; C = g_kv; ldc = 1024; }
  else if constexpr (MODE == 2) { A = pA; lda = 512; K = 512; B = pB; ldb = 512; C = g_posp; ldc = 1024; }
  else if constexpr (MODE == 3) { bb = z >> 3; e = z & 7;
    A = g_q + (long)bb * 512 + e * 64; lda = 65536; K = 64;
    B = g_kv + (long)bb * 1024 + e * 64; ldb = 131072;
    C = g_A12 + (long)e * 8388608 + (long)bb * 256; ldc = 32768; }
  else if constexpr (MODE == 4) { e = z >> 8; bb = z & 255;
    A = g_q + (long)bb * 65536 + e * 64; lda = 512; K = 64;
    C = g_A12 + (long)e * 8388608 + (long)bb * 32768; ldc = 256; }
  else if constexpr (MODE == 5) { e = z >> 8; bb = z & 255;
    B = g_kv + (long)bb * 131072 + e * 64; ldb = 1024; K = 64;
    C = g_T3 + ((long)e * 256 + bb) * 32768; ldc = 128; }
  else if constexpr (MODE == 6) { bb = z >> 3; e = z & 7;
    A = g_A12 + (long)e * 8388608 + (long)bb * 256; lda = 32768; K = 256;
    B = g_kv + (long)bb * 1024 + 512 + e * 64; ldb = 131072;
    C = g_vo + (long)bb * 512 + e * 64; ldc = 65536; }
  else { A = g_vo; lda = 512; K = 512; B = pB; ldb = 512; C = pC; ldc = 512; }

  float4 ra[NA], rb[NB];

  auto loadA = [&](int k0) {
#pragma unroll
    for (int it = 0; it < NA; ++it) {
      int t = (tid + it * 256) * 4;
      int i = t >> 4, kk = t & 15;
      if constexpr (MODE == 5) {
        int gi = pidx[(i0 + i) * 256 + bb];
        ra[it] = ld4(g_posp + (long)gi * 1024 + e * 64 + k0 + kk);
      } else if constexpr (MODE == 2) {
        ra[it] = (i0 + i < 511) ? ld4(A + (long)(i0 + i) * lda + k0 + kk)
                                : make_float4(0.f, 0.f, 0.f, 0.f);
      } else {
        ra[it] = ld4(A + (long)(i0 + i) * lda + k0 + kk);
      }
    }
  };
  auto storeA = [&](unsigned* dst) {
#pragma unroll
    for (int it = 0; it < NA; ++it) {
      int t = (tid + it * 256) * 4;
      int i = t >> 4, kk = t & 15;
      *reinterpret_cast<uint4*>(&dst[i * 20 + kk]) =
          make_uint4(f2tf(ra[it].x), f2tf(ra[it].y), f2tf(ra[it].z), f2tf(ra[it].w));
    }
  };
  auto loadB = [&](int k0) {
#pragma unroll
    for (int it = 0; it < NB; ++it) {
      int t = (tid + it * 256) * 4;
      if constexpr (MODE == 6) {
        int kk = t / BN, j = t % BN;
        rb[it] = ld4(B + (long)(k0 + kk) * ldb + j0 + j);
      } else if constexpr (MODE == 4) {
        int j = t >> 4, kk = t & 15;
        int gi = pidx[bb * 256 + j0 + j];
        rb[it] = ld4(g_posp + (long)gi * 1024 + 512 + e * 64 + k0 + kk);
      } else {
        int j = t >> 4, kk = t & 15;
        rb[it] = ld4(B + (long)(j0 + j) * ldb + k0 + kk);
      }
    }
  };
  auto storeB = [&](unsigned* dst) {
#pragma unroll
    for (int it = 0; it < NB; ++it) {
      int t = (tid + it * 256) * 4;
      uint4 u = make_uint4(f2tf(rb[it].x), f2tf(rb[it].y), f2tf(rb[it].z), f2tf(rb[it].w));
      if constexpr (MODE == 6) {
        int kk = t / BN, j = t % BN;
        *reinterpret_cast<uint4*>(&dst[kk * 136 + j]) = u;
      } else {
        int j = t >> 4, kk = t & 15;
        *reinterpret_cast<uint4*>(&dst[j * 20 + kk]) = u;
      }
    }
  };

  float acc[MT][4][4];
#pragma unroll
  for (int m = 0; m < MT; ++m)
#pragma unroll
    for (int n = 0; n < 4; ++n)
#pragma unroll
      for (int r = 0; r < 4; ++r) acc[m][n][r] = 0.f;

  const int NIT = K / 16;
  loadA(0); loadB(0);
  storeA(As); storeB(Bs);
  __syncthreads();

  for (int itn = 0; itn < NIT; ++itn) {
    const int cur = itn & 1;
    if (itn + 1 < NIT) { loadA((itn + 1) * 16); loadB((itn + 1) * 16); }
    const unsigned* ap = As + cur * ASZ;
    const unsigned* bp = Bs + cur * BSZ;
#pragma unroll
    for (int ks = 0; ks < 2; ++ks) {
      const int kb = ks * 8;
      unsigned a[MT][4], b[4][2];
#pragma unroll
      for (int mt = 0; mt < MT; ++mt) {
        int r = wm0 + mt * 16 + gid;
        a[mt][0] = ap[r * 20 + kb + tg];
        a[mt][1] = ap[(r + 8) * 20 + kb + tg];
        a[mt][2] = ap[r * 20 + kb + tg + 4];
        a[mt][3] = ap[(r + 8) * 20 + kb + tg + 4];
      }
#pragma unroll
      for (int nt = 0; nt < 4; ++nt) {
        int cn = wn0 + nt * 8 + gid;
        if constexpr (MODE == 6) {
          b[nt][0] = bp[(kb + tg) * 136 + cn];
          b[nt][1] = bp[(kb + tg + 4) * 136 + cn];
        } else {
          b[nt][0] = bp[cn * 20 + kb + tg];
          b[nt][1] = bp[cn * 20 + kb + tg + 4];
        }
      }
#pragma unroll
      for (int mt = 0; mt < MT; ++mt)
#pragma unroll
        for (int nt = 0; nt < 4; ++nt) mma8(acc[mt][nt], a[mt], b[nt]);
    }
    if (itn + 1 < NIT) {
      storeA(As + (cur ^ 1) * ASZ);
      storeB(Bs + (cur ^ 1) * BSZ);
      __syncthreads();
    }
  }

  // ---- epilogue ----
#pragma unroll
  for (int mt = 0; mt < MT; ++mt) {
#pragma unroll
    for (int nt = 0; nt < 4; ++nt) {
      int j = j0 + wn0 + nt * 8 + 2 * tg;
#pragma unroll
      for (int h = 0; h < 2; ++h) {
        int i = i0 + wm0 + mt * 16 + gid + h * 8;
        if constexpr (MODE == 2) { if (i >= 511) continue; }
        float v0 = acc[mt][nt][h * 2 + 0];
        float v1 = acc[mt][nt][h * 2 + 1];
        float* cp = C + (long)i * ldc + j;
        if constexpr (MODE == 0) {
          float2 bv = *reinterpret_cast<const float2*>(pbias + j);
          v0 = (v0 + bv.x) * 0.125f; v1 = (v1 + bv.y) * 0.125f;
        } else if constexpr (MODE == 1) {
          float2 bv = *reinterpret_cast<const float2*>(pbias + j);
          v0 += bv.x; v1 += bv.y;
        } else if constexpr (MODE == 2) {
          float2 bv = *reinterpret_cast<const float2*>(pbias + j);
          float sc = (j < 512) ? 0.125f : 1.0f;
          v0 = (v0 + bv.x) * sc; v1 = (v1 + bv.y) * sc;
        } else if constexpr (MODE == 4) {
          float2 o = *reinterpret_cast<const float2*>(cp);
          v0 += o.x; v1 += o.y;
        } else if constexpr (MODE == 7) {
          float2 bv = *reinterpret_cast<const float2*>(pbias + j);
          float2 rv = *reinterpret_cast<const float2*>(presid + (long)i * 512 + j);
          v0 += bv.x + rv.x; v1 += bv.y + rv.y;
        }
        *reinterpret_cast<float2*>(cp) = make_float2(v0, v1);
      }
    }
  }
}

// ------- Fused: A12 += T3^T, raw = sum_e, softmax, all in one pass -------
// block = (w, n-chunk of 16). smem S[128 rows = e*16+nn][257] fp32.
__global__ void __launch_bounds__(256) fused_t3_sm_kernel(float* __restrict__ out2) {
  extern __shared__ float S[];
  const int w  = blockIdx.x;
  const int n0 = blockIdx.y * 16;
  const int tid = threadIdx.x;

  // 1. load A12[e][w][n0:n0+16][:]
  for (int idx = tid * 4; idx < 8 * 16 * 256; idx += 1024) {
    int e = idx >> 12, nn = (idx >> 8) & 15, v = idx & 255;
    float4 x = ld4(g_A12 + (long)e * 8388608 + (long)w * 32768 + (n0 + nn) * 256 + v);
    float* s = S + (e * 16 + nn) * 257 + v;
    s[0] = x.x; s[1] = x.y; s[2] = x.z; s[3] = x.w;
  }
  __syncthreads();

  // 2. S[e][n][v] += T3[e][v][w][n]
  for (int idx = tid * 4; idx < 8 * 256 * 16; idx += 1024) {
    int e = idx >> 12, v = (idx >> 4) & 255, ni = idx & 15;  // ni in {0,4,8,12}
    float4 x = ld4(g_T3 + ((long)e * 256 + v) * 32768 + (long)w * 128 + n0 + ni);
    S[(e * 16 + ni + 0) * 257 + v] += x.x;
    S[(e * 16 + ni + 1) * 257 + v] += x.y;
    S[(e * 16 + ni + 2) * 257 + v] += x.z;
    S[(e * 16 + ni + 3) * 257 + v] += x.w;
  }
  __syncthreads();

  // 3. raw_attn[n][w][v] = sum_e S
  for (int idx = tid; idx < 16 * 256; idx += 256) {
    int nn = idx >> 8, v = idx & 255;
    float s = 0.f;
#pragma unroll
    for (int e = 0; e < 8; ++e) s += S[(e * 16 + nn) * 257 + v];
    out2[((long)(n0 + nn) * 256 + w) * 256 + v] = s;
  }

  // 4. softmax per (e,nn) row -> write probs to A12
  const int warp = tid >> 5, lane = tid & 31;
  for (int r = warp; r < 128; r += 8) {
    int e = r >> 4, nn = r & 15;
    const float* row = S + r * 257;
    float x[8];
    float mx = -1e30f;
#pragma unroll
    for (int j = 0; j < 8; ++j) { x[j] = row[lane + j * 32]; mx = fmaxf(mx, x[j]); }
#pragma unroll
    for (int o = 16; o > 0; o >>= 1) mx = fmaxf(mx, __shfl_xor_sync(0xffffffffu, mx, o));
    float s = 0.f;
#pragma unroll
    for (int j = 0; j < 8; ++j) { x[j] = __expf(x[j] - mx); s += x[j]; }
#pragma unroll
    for (int o = 16; o > 0; o >>= 1) s += __shfl_xor_sync(0xffffffffu, s, o);
    float inv = 1.0f / s;
    float* dst = g_A12 + (long)e * 8388608 + (long)w * 32768 + (n0 + nn) * 256;
#pragma unroll
    for (int j = 0; j < 8; ++j) dst[lane + j * 32] = x[j] * inv;
  }
}

extern "C" void kernel_launch(void* const* d_in, const int* in_sizes, int n_in,
                              void* d_out, int out_size) {
  const float* feat_left   = (const float*)d_in[0];
  const float* feat_right  = (const float*)d_in[1];
  const float* pos         = (const float*)d_in[2];
  const int*   pos_indexes = (const int*)d_in[3];
  const float* ln_w        = (const float*)d_in[4];
  const float* ln_b        = (const float*)d_in[5];
  const float* in_proj_w   = (const float*)d_in[6];
  const float* in_proj_b   = (const float*)d_in[7];
  const float* out_w       = (const float*)d_in[8];
  const float* out_b       = (const float*)d_in[9];
  float* out = (float*)d_out;

  cudaFuncSetAttribute(fused_t3_sm_kernel,
                       cudaFuncAttributeMaxDynamicSharedMemorySize, 128 * 257 * 4);

  ln_kernel<<<65536, 128>>>(feat_left, feat_right, ln_w, ln_b);

  gemm_k<0, 128, 128><<<dim3(4, 256, 1), 256>>>(
      nullptr, in_proj_w, in_proj_b, nullptr, nullptr, nullptr);
  gemm_k<1, 128, 128><<<dim3(8, 256, 1), 256>>>(
      nullptr, in_proj_w + 512 * 512, in_proj_b + 512, nullptr, nullptr, nullptr);
  gemm_k<2, 64, 64><<<dim3(16, 8, 1), 256>>>(
      pos, in_proj_w, in_proj_b, nullptr, nullptr, nullptr);

  gemm_k<3, 128, 128><<<dim3(2, 2, 1024), 256>>>(
      nullptr, nullptr, nullptr, nullptr, nullptr, nullptr);
  gemm_k<4, 128, 128><<<dim3(2, 1, 2048), 256>>>(
      nullptr, nullptr, nullptr, nullptr, pos_indexes, nullptr);
  gemm_k<5, 128, 128><<<dim3(1, 2, 2048), 256>>>(
      nullptr, nullptr, nullptr, nullptr, pos_indexes, nullptr);

  fused_t3_sm_kernel<<<dim3(256, 8), 256, 128 * 257 * 4>>>(out + 16777216);

  gemm_k<6, 128, 64><<<dim3(1, 2, 1024), 256>>>(
      nullptr, nullptr, nullptr, nullptr, nullptr, nullptr);
  gemm_k<7, 128, 128><<<dim3(4, 256, 1), 256>>>(
      nullptr, out_w, out_b, feat_left, nullptr, out);
}

// round 5
// speedup vs baseline: 1.1315x; 1.1315x over previous
#include <cuda_runtime.h>

static constexpr long kQSize = 256L * 128 * 512;        // 16,777,216
static constexpr long kAttn  = 8L * 256 * 128 * 256;    // 67,108,864

__device__ float g_lnL[kQSize];
__device__ float g_lnR[kQSize];
__device__ float g_q[kQSize];          // [w][n][c], pre-scaled by 0.125
__device__ float g_kv[2 * kQSize];     // [w][n][k(0:512)|v(512:1024)]
__device__ float g_posp[511 * 1024];   // [p][q_r*0.125 (0:512) | k_r (512:1024)]
__device__ float g_vo[kQSize];         // [w][n][c]
__device__ float g_A12[kAttn];         // [e][w][n][v]  scores -> probs
__device__ float g_T3[kAttn];          // [e][v][w][n]

__device__ __forceinline__ float4 ld4(const float* p) {
  return *reinterpret_cast<const float4*>(p);
}
__device__ __forceinline__ unsigned f2tf(float x) {
  unsigned r;
  asm("cvt.rna.tf32.f32 %0, %1;" : "=r"(r) : "f"(x));
  return r;
}
__device__ __forceinline__ void mma8(float (&d)[4], const unsigned (&a)[4],
                                     const unsigned (&b)[2]) {
  asm("mma.sync.aligned.m16n8k8.row.col.f32.tf32.tf32.f32 "
      "{%0,%1,%2,%3}, {%4,%5,%6,%7}, {%8,%9}, {%0,%1,%2,%3};"
      : "+f"(d[0]), "+f"(d[1]), "+f"(d[2]), "+f"(d[3])
      : "r"(a[0]), "r"(a[1]), "r"(a[2]), "r"(a[3]), "r"(b[0]), "r"(b[1]));
}

// ---------------- LayerNorm: one block per 512-float row ----------------
__global__ void __launch_bounds__(128) ln_kernel(const float* __restrict__ fl,
                                                 const float* __restrict__ fr,
                                                 const float* __restrict__ lw,
                                                 const float* __restrict__ lb) {
  long row = blockIdx.x;
  const float* src;
  float* dst;
  if (row < 32768) { src = fl + row * 512;           dst = g_lnL + row * 512; }
  else             { src = fr + (row - 32768) * 512; dst = g_lnR + (row - 32768) * 512; }
  int t = threadIdx.x;
  float4 x = ld4(src + t * 4);
  float s  = x.x + x.y + x.z + x.w;
  float q2 = x.x * x.x + x.y * x.y + x.z * x.z + x.w * x.w;
#pragma unroll
  for (int o = 16; o > 0; o >>= 1) {
    s  += __shfl_xor_sync(0xffffffffu, s, o);
    q2 += __shfl_xor_sync(0xffffffffu, q2, o);
  }
  __shared__ float ss[4], sq[4];
  if ((t & 31) == 0) { ss[t >> 5] = s; sq[t >> 5] = q2; }
  __syncthreads();
  s  = ss[0] + ss[1] + ss[2] + ss[3];
  q2 = sq[0] + sq[1] + sq[2] + sq[3];
  float mean = s * (1.f / 512.f);
  float var  = q2 * (1.f / 512.f) - mean * mean;
  float rstd = rsqrtf(var + 1e-5f);
  float4 wv = ld4(lw + t * 4), bv = ld4(lb + t * 4);
  float4 o;
  o.x = (x.x - mean) * rstd * wv.x + bv.x;
  o.y = (x.y - mean) * rstd * wv.y + bv.y;
  o.z = (x.z - mean) * rstd * wv.z + bv.z;
  o.w = (x.w - mean) * rstd * wv.w + bv.w;
  *reinterpret_cast<float4*>(dst + t * 4) = o;
}

// ---------------- Tensor-core tf32 GEMM, specialized by MODE ----------------
// 0: q = lnL@Wq^T (+b)*0.125 -> g_q         1: kv = lnR@Wkv^T + b -> g_kv
// 2: posp = pos@W[:1024]^T + b (cols<512 *0.125), M=511 guarded -> g_posp
// 3: T1 per (n,e): q.k^T -> A12             4: T2 per (e,w): q.kr^T += A12 (gather B)
// 5: T3 per (e,v): qr.k^T -> T3 (gather A)  6: AV per (n,e): P@V (NN) -> g_vo
// 7: out = vo@Wo^T + b + resid -> d_out
template <int MODE, int BM, int BN>
__global__ void __launch_bounds__(256)
gemm_k(const float* __restrict__ pA, const float* __restrict__ pB,
       const float* __restrict__ pbias, const float* __restrict__ presid,
       const int* __restrict__ pidx, float* __restrict__ pC) {
  constexpr int WGN = BN / 32;       // warps along n
  constexpr int WGM = 8 / WGN;       // warps along m
  constexpr int WM  = BM / WGM;      // rows per warp
  constexpr int MT  = WM / 16;       // 16-row mma tiles per warp
  __shared__ unsigned As[BM * 20];
  __shared__ unsigned Bs[(MODE == 6) ? 16 * 136 : BN * 20];

  const int tid   = threadIdx.x;
  const int warp  = tid >> 5;
  const int lane  = tid & 31;
  const int gid   = lane >> 2;
  const int tg    = lane & 3;
  const int wm0   = (warp / WGN) * WM;
  const int wn0   = (warp % WGN) * 32;
  const int i0 = blockIdx.y * BM;
  const int j0 = blockIdx.x * BN;
  const int z  = blockIdx.z;

  const float* A = nullptr;
  const float* B = nullptr;
  float* C = nullptr;
  long lda = 0, ldb = 0, ldc = 0;
  int K = 0, e = 0, bb = 0;

  if constexpr (MODE == 0) { A = g_lnL; lda = 512; K = 512; B = pB; ldb = 512; C = g_q; ldc = 512; }
  else if constexpr (MODE == 1) { A = g_lnR; lda = 512; K = 512; B = pB; ldb = 512; C = g_kv; ldc = 1024; }
  else if constexpr (MODE == 2) { A = pA; lda = 512; K = 512; B = pB; ldb = 512; C = g_posp; ldc = 1024; }
  else if constexpr (MODE == 3) { bb = z >> 3; e = z & 7;
    A = g_q + (long)bb * 512 + e * 64; lda = 65536; K = 64;
    B = g_kv + (long)bb * 1024 + e * 64; ldb = 131072;
    C = g_A12 + (long)e * 8388608 + (long)bb * 256; ldc = 32768; }
  else if constexpr (MODE == 4) { e = z >> 8; bb = z & 255;
    A = g_q + (long)bb * 65536 + e * 64; lda = 512; K = 64;
    C = g_A12 + (long)e * 8388608 + (long)bb * 32768; ldc = 256; }
  else if constexpr (MODE == 5) { e = z >> 8; bb = z & 255;
    B = g_kv + (long)bb * 131072 + e * 64; ldb = 1024; K = 64;
    C = g_T3 + ((long)e * 256 + bb) * 32768; ldc = 128; }
  else if constexpr (MODE == 6) { bb = z >> 3; e = z & 7;
    A = g_A12 + (long)e * 8388608 + (long)bb * 256; lda = 32768; K = 256;
    B = g_kv + (long)bb * 1024 + 512 + e * 64; ldb = 131072;
    C = g_vo + (long)bb * 512 + e * 64; ldc = 65536; }
  else { A = g_vo; lda = 512; K = 512; B = pB; ldb = 512; C = pC; ldc = 512; }

  float acc[MT][4][4];
#pragma unroll
  for (int m = 0; m < MT; ++m)
#pragma unroll
    for (int n = 0; n < 4; ++n)
#pragma unroll
      for (int r = 0; r < 4; ++r) acc[m][n][r] = 0.f;

  for (int k0 = 0; k0 < K; k0 += 16) {
    // ---- A tile: BM x 16, stored As[i][k] with tf32 conversion ----
#pragma unroll
    for (int it = 0; it < (BM * 16) / 1024; ++it) {
      int t = (tid + it * 256) * 4;
      int i = t >> 4, kk = t & 15;
      float4 v4;
      if constexpr (MODE == 5) {
        int gi = pidx[(i0 + i) * 256 + bb];
        v4 = ld4(g_posp + (long)gi * 1024 + e * 64 + k0 + kk);
      } else if constexpr (MODE == 2) {
        v4 = (i0 + i < 511) ? ld4(A + (long)(i0 + i) * lda + k0 + kk)
                            : make_float4(0.f, 0.f, 0.f, 0.f);
      } else {
        v4 = ld4(A + (long)(i0 + i) * lda + k0 + kk);
      }
      *reinterpret_cast<uint4*>(&As[i * 20 + kk]) =
          make_uint4(f2tf(v4.x), f2tf(v4.y), f2tf(v4.z), f2tf(v4.w));
    }
    // ---- B tile ----
    if constexpr (MODE == 6) {  // NN: global B[k][j] -> Bs[k*136 + j]
#pragma unroll
      for (int it = 0; it < (16 * BN) / 1024; ++it) {
        int t = (tid + it * 256) * 4;
        int kk = t / BN, j = t % BN;
        float4 v4 = ld4(B + (long)(k0 + kk) * ldb + j0 + j);
        *reinterpret_cast<uint4*>(&Bs[kk * 136 + j]) =
            make_uint4(f2tf(v4.x), f2tf(v4.y), f2tf(v4.z), f2tf(v4.w));
      }
    } else {
#pragma unroll
      for (int it = 0; it < (BN * 16) / 1024; ++it) {
        int t = (tid + it * 256) * 4;
        int j = t >> 4, kk = t & 15;
        float4 v4;
        if constexpr (MODE == 4) {
          int gi = pidx[bb * 256 + j0 + j];
          v4 = ld4(g_posp + (long)gi * 1024 + 512 + e * 64 + k0 + kk);
        } else {
          v4 = ld4(B + (long)(j0 + j) * ldb + k0 + kk);
        }
        *reinterpret_cast<uint4*>(&Bs[j * 20 + kk]) =
            make_uint4(f2tf(v4.x), f2tf(v4.y), f2tf(v4.z), f2tf(v4.w));
      }
    }
    __syncthreads();

#pragma unroll
    for (int ks = 0; ks < 2; ++ks) {
      const int kb = ks * 8;
      unsigned a[MT][4], b[4][2];
#pragma unroll
      for (int mt = 0; mt < MT; ++mt) {
        int r = wm0 + mt * 16 + gid;
        a[mt][0] = As[r * 20 + kb + tg];
        a[mt][1] = As[(r + 8) * 20 + kb + tg];
        a[mt][2] = As[r * 20 + kb + tg + 4];
        a[mt][3] = As[(r + 8) * 20 + kb + tg + 4];
      }
#pragma unroll
      for (int nt = 0; nt < 4; ++nt) {
        int cn = wn0 + nt * 8 + gid;
        if constexpr (MODE == 6) {
          b[nt][0] = Bs[(kb + tg) * 136 + cn];
          b[nt][1] = Bs[(kb + tg + 4) * 136 + cn];
        } else {
          b[nt][0] = Bs[cn * 20 + kb + tg];
          b[nt][1] = Bs[cn * 20 + kb + tg + 4];
        }
      }
#pragma unroll
      for (int mt = 0; mt < MT; ++mt)
#pragma unroll
        for (int nt = 0; nt < 4; ++nt) mma8(acc[mt][nt], a[mt], b[nt]);
    }
    __syncthreads();
  }

  // ---- epilogue: each thread owns pairs (i, j), (i, j+1) and (i+8, ...) ----
#pragma unroll
  for (int mt = 0; mt < MT; ++mt) {
#pragma unroll
    for (int nt = 0; nt < 4; ++nt) {
      int j = j0 + wn0 + nt * 8 + 2 * tg;
#pragma unroll
      for (int h = 0; h < 2; ++h) {
        int i = i0 + wm0 + mt * 16 + gid + h * 8;
        if constexpr (MODE == 2) { if (i >= 511) continue; }
        float v0 = acc[mt][nt][h * 2 + 0];
        float v1 = acc[mt][nt][h * 2 + 1];
        float* cp = C + (long)i * ldc + j;
        if constexpr (MODE == 0) {
          float2 bv = *reinterpret_cast<const float2*>(pbias + j);
          v0 = (v0 + bv.x) * 0.125f; v1 = (v1 + bv.y) * 0.125f;
        } else if constexpr (MODE == 1) {
          float2 bv = *reinterpret_cast<const float2*>(pbias + j);
          v0 += bv.x; v1 += bv.y;
        } else if constexpr (MODE == 2) {
          float2 bv = *reinterpret_cast<const float2*>(pbias + j);
          float sc = (j < 512) ? 0.125f : 1.0f;
          v0 = (v0 + bv.x) * sc; v1 = (v1 + bv.y) * sc;
        } else if constexpr (MODE == 4) {
          float2 o = *reinterpret_cast<const float2*>(cp);
          v0 += o.x; v1 += o.y;
        } else if constexpr (MODE == 7) {
          float2 bv = *reinterpret_cast<const float2*>(pbias + j);
          float2 rv = *reinterpret_cast<const float2*>(presid + (long)i * 512 + j);
          v0 += bv.x + rv.x; v1 += bv.y + rv.y;
        }
        *reinterpret_cast<float2*>(cp) = make_float2(v0, v1);
      }
    }
  }
}

// ---------------- T3 transpose-add: A12[e][w][n][v] += T3[e][v][w][n] ----------------
__global__ void __launch_bounds__(256) t3_add_kernel() {
  int w = blockIdx.x, e = blockIdx.y;
  __shared__ float ts[32][129];
  long a12base = (long)e * 8388608 + (long)w * 32768;
  long t3base  = (long)e * 256 * 32768 + (long)w * 128;
  for (int v0 = 0; v0 < 256; v0 += 32) {
    for (int t = threadIdx.x; t < 32 * 128; t += 256) {
      int vj = t >> 7, n = t & 127;
      ts[vj][n] = g_T3[t3base + (long)(v0 + vj) * 32768 + n];
    }
    __syncthreads();
    for (int t = threadIdx.x; t < 32 * 128; t += 256) {
      int n = t >> 5, vj = t & 31;
      g_A12[a12base + n * 256 + v0 + vj] += ts[vj][n];
    }
    __syncthreads();
  }
}

// ------- Merged raw_attn + softmax, zero smem -------
// grid (256 w, 16), block 256 = 8 warps; warp handles one n row (n0 + warp).
// For each e: stream row A12[e][w][n][0:256] (8 floats/lane), softmax it in
// registers, write probs back, accumulate pre-softmax values into raw sum.
__global__ void __launch_bounds__(256) raw_sm_kernel(float* __restrict__ out2) {
  const int w    = blockIdx.x;
  const int n    = blockIdx.y * 8 + (threadIdx.x >> 5);
  const int lane = threadIdx.x & 31;

  float raw0 = 0.f, raw1 = 0.f, raw2 = 0.f, raw3 = 0.f;
  float raw4 = 0.f, raw5 = 0.f, raw6 = 0.f, raw7 = 0.f;

#pragma unroll
  for (int e = 0; e < 8; ++e) {
    float* p = g_A12 + (long)e * 8388608 + (long)w * 32768 + n * 256;
    float4 a = ld4(p + lane * 4);
    float4 b = ld4(p + 128 + lane * 4);
    raw0 += a.x; raw1 += a.y; raw2 += a.z; raw3 += a.w;
    raw4 += b.x; raw5 += b.y; raw6 += b.z; raw7 += b.w;
    float mx = fmaxf(fmaxf(fmaxf(a.x, a.y), fmaxf(a.z, a.w)),
                     fmaxf(fmaxf(b.x, b.y), fmaxf(b.z, b.w)));
#pragma unroll
    for (int o = 16; o > 0; o >>= 1) mx = fmaxf(mx, __shfl_xor_sync(0xffffffffu, mx, o));
    a.x = __expf(a.x - mx); a.y = __expf(a.y - mx);
    a.z = __expf(a.z - mx); a.w = __expf(a.w - mx);
    b.x = __expf(b.x - mx); b.y = __expf(b.y - mx);
    b.z = __expf(b.z - mx); b.w = __expf(b.w - mx);
    float s = a.x + a.y + a.z + a.w + b.x + b.y + b.z + b.w;
#pragma unroll
    for (int o = 16; o > 0; o >>= 1) s += __shfl_xor_sync(0xffffffffu, s, o);
    float inv = 1.0f / s;
    a.x *= inv; a.y *= inv; a.z *= inv; a.w *= inv;
    b.x *= inv; b.y *= inv; b.z *= inv; b.w *= inv;
    *reinterpret_cast<float4*>(p + lane * 4) = a;
    *reinterpret_cast<float4*>(p + 128 + lane * 4) = b;
  }

  float* rp = out2 + ((long)n * 256 + w) * 256;
  *reinterpret_cast<float4*>(rp + lane * 4) = make_float4(raw0, raw1, raw2, raw3);
  *reinterpret_cast<float4*>(rp + 128 + lane * 4) = make_float4(raw4, raw5, raw6, raw7);
}

extern "C" void kernel_launch(void* const* d_in, const int* in_sizes, int n_in,
                              void* d_out, int out_size) {
  const float* feat_left   = (const float*)d_in[0];
  const float* feat_right  = (const float*)d_in[1];
  const float* pos         = (const float*)d_in[2];
  const int*   pos_indexes = (const int*)d_in[3];
  const float* ln_w        = (const float*)d_in[4];
  const float* ln_b        = (const float*)d_in[5];
  const float* in_proj_w   = (const float*)d_in[6];
  const float* in_proj_b   = (const float*)d_in[7];
  const float* out_w       = (const float*)d_in[8];
  const float* out_b       = (const float*)d_in[9];
  float* out = (float*)d_out;

  ln_kernel<<<65536, 128>>>(feat_left, feat_right, ln_w, ln_b);

  gemm_k<0, 128, 128><<<dim3(4, 256, 1), 256>>>(
      nullptr, in_proj_w, in_proj_b, nullptr, nullptr, nullptr);
  gemm_k<1, 128, 128><<<dim3(8, 256, 1), 256>>>(
      nullptr, in_proj_w + 512 * 512, in_proj_b + 512, nullptr, nullptr, nullptr);
  gemm_k<2, 64, 64><<<dim3(16, 8, 1), 256>>>(
      pos, in_proj_w, in_proj_b, nullptr, nullptr, nullptr);

  gemm_k<3, 128, 128><<<dim3(2, 2, 1024), 256>>>(
      nullptr, nullptr, nullptr, nullptr, nullptr, nullptr);
  gemm_k<4, 128, 128><<<dim3(2, 1, 2048), 256>>>(
      nullptr, nullptr, nullptr, nullptr, pos_indexes, nullptr);
  gemm_k<5, 128, 128><<<dim3(1, 2, 2048), 256>>>(
      nullptr, nullptr, nullptr, nullptr, pos_indexes, nullptr);

  t3_add_kernel<<<dim3(256, 8), 256>>>();
  raw_sm_kernel<<<dim3(256, 16), 256>>>(out + 16777216);

  gemm_k<6, 128, 64><<<dim3(1, 2, 1024), 256>>>(
      nullptr, nullptr, nullptr, nullptr, nullptr, nullptr);
  gemm_k<7, 128, 128><<<dim3(4, 256, 1), 256>>>(
      nullptr, out_w, out_b, feat_left, nullptr, out);
}

// round 6
// speedup vs baseline: 1.1639x; 1.0286x over previous
#include <cuda_runtime.h>

static constexpr long kQSize = 256L * 128 * 512;        // 16,777,216
static constexpr long kAttn  = 8L * 256 * 128 * 256;    // 67,108,864

__device__ float g_lnL[kQSize];
__device__ float g_lnR[kQSize];
__device__ float g_q[kQSize];          // [w][n][c], pre-scaled by 0.125
__device__ float g_kv[2 * kQSize];     // [w][n][k(0:512)|v(512:1024)]
__device__ float g_posp[511 * 1024];   // [p][q_r*0.125 (0:512) | k_r (512:1024)]
__device__ float g_vo[kQSize];         // [w][n][c]
__device__ float g_A12[kAttn];         // [e][w][n][v]  scores -> probs
__device__ float g_T3[kAttn];          // [e][v][w][n]

__device__ __forceinline__ float4 ld4(const float* p) {
  return *reinterpret_cast<const float4*>(p);
}
__device__ __forceinline__ unsigned f2tf(float x) {
  unsigned r;
  asm("cvt.rna.tf32.f32 %0, %1;" : "=r"(r) : "f"(x));
  return r;
}
__device__ __forceinline__ void mma8(float (&d)[4], const unsigned (&a)[4],
                                     const unsigned (&b)[2]) {
  asm("mma.sync.aligned.m16n8k8.row.col.f32.tf32.tf32.f32 "
      "{%0,%1,%2,%3}, {%4,%5,%6,%7}, {%8,%9}, {%0,%1,%2,%3};"
      : "+f"(d[0]), "+f"(d[1]), "+f"(d[2]), "+f"(d[3])
      : "r"(a[0]), "r"(a[1]), "r"(a[2]), "r"(a[3]), "r"(b[0]), "r"(b[1]));
}
__device__ __forceinline__ void cpa16(float* smem_dst, const float* g, bool pred) {
  unsigned d = (unsigned)__cvta_generic_to_shared(smem_dst);
  int sz = pred ? 16 : 0;
  asm volatile("cp.async.cg.shared.global [%0], [%1], 16, %2;"
               :: "r"(d), "l"(g), "r"(sz));
}
__device__ __forceinline__ void cpa_commit() {
  asm volatile("cp.async.commit_group;" ::: "memory");
}
__device__ __forceinline__ void cpa_wait1() {
  asm volatile("cp.async.wait_group 1;" ::: "memory");
}

// ---------------- LayerNorm: one block per 512-float row ----------------
__global__ void __launch_bounds__(128) ln_kernel(const float* __restrict__ fl,
                                                 const float* __restrict__ fr,
                                                 const float* __restrict__ lw,
                                                 const float* __restrict__ lb) {
  long row = blockIdx.x;
  const float* src;
  float* dst;
  if (row < 32768) { src = fl + row * 512;           dst = g_lnL + row * 512; }
  else             { src = fr + (row - 32768) * 512; dst = g_lnR + (row - 32768) * 512; }
  int t = threadIdx.x;
  float4 x = ld4(src + t * 4);
  float s  = x.x + x.y + x.z + x.w;
  float q2 = x.x * x.x + x.y * x.y + x.z * x.z + x.w * x.w;
#pragma unroll
  for (int o = 16; o > 0; o >>= 1) {
    s  += __shfl_xor_sync(0xffffffffu, s, o);
    q2 += __shfl_xor_sync(0xffffffffu, q2, o);
  }
  __shared__ float ss[4], sq[4];
  if ((t & 31) == 0) { ss[t >> 5] = s; sq[t >> 5] = q2; }
  __syncthreads();
  s  = ss[0] + ss[1] + ss[2] + ss[3];
  q2 = sq[0] + sq[1] + sq[2] + sq[3];
  float mean = s * (1.f / 512.f);
  float var  = q2 * (1.f / 512.f) - mean * mean;
  float rstd = rsqrtf(var + 1e-5f);
  float4 wv = ld4(lw + t * 4), bv = ld4(lb + t * 4);
  float4 o;
  o.x = (x.x - mean) * rstd * wv.x + bv.x;
  o.y = (x.y - mean) * rstd * wv.y + bv.y;
  o.z = (x.z - mean) * rstd * wv.z + bv.z;
  o.w = (x.w - mean) * rstd * wv.w + bv.w;
  *reinterpret_cast<float4*>(dst + t * 4) = o;
}

// ------------- Tensor-core tf32 GEMM, 3-stage cp.async pipeline -------------
// 0: q = lnL@Wq^T (+b)*0.125 -> g_q         1: kv = lnR@Wkv^T + b -> g_kv
// 2: posp = pos@W[:1024]^T + b (cols<512 *0.125), M=511 guarded -> g_posp
// 3: T1 per (n,e): q.k^T -> A12             4: T2 per (e,w): q.kr^T += A12 (gather B)
// 5: T3 per (e,v): qr.k^T -> T3 (gather A)  6: AV per (n,e): P@V (NN) -> g_vo
// 7: out = vo@Wo^T + b + resid -> d_out
template <int MODE, int BM, int BN>
__global__ void __launch_bounds__(256)
gemm_k(const float* __restrict__ pA, const float* __restrict__ pB,
       const float* __restrict__ pbias, const float* __restrict__ presid,
       const int* __restrict__ pidx, float* __restrict__ pC) {
  constexpr int WGN = BN / 32;       // warps along n
  constexpr int WGM = 8 / WGN;       // warps along m
  constexpr int WM  = BM / WGM;      // rows per warp
  constexpr int MT  = WM / 16;       // 16-row mma tiles per warp
  constexpr int ASZ = BM * 20;       // floats per A stage
  constexpr int BSZ = (MODE == 6) ? 16 * 136 : BN * 20;
  constexpr int NA  = (BM * 16) / 1024;   // cp.async per thread (A)
  constexpr int NB  = (BN * 16) / 1024;   // cp.async per thread (B)
  extern __shared__ float dsm[];
  float* Asm = dsm;                  // [3][ASZ]
  float* Bsm = dsm + 3 * ASZ;        // [3][BSZ]

  const int tid   = threadIdx.x;
  const int warp  = tid >> 5;
  const int lane  = tid & 31;
  const int gid   = lane >> 2;
  const int tg    = lane & 3;
  const int wm0   = (warp / WGN) * WM;
  const int wn0   = (warp % WGN) * 32;
  const int i0 = blockIdx.y * BM;
  const int j0 = blockIdx.x * BN;
  const int z  = blockIdx.z;

  const float* A = nullptr;
  const float* B = nullptr;
  float* C = nullptr;
  long lda = 0, ldb = 0, ldc = 0;
  int K = 0, e = 0, bb = 0;

  if constexpr (MODE == 0) { A = g_lnL; lda = 512; K = 512; B = pB; ldb = 512; C = g_q; ldc = 512; }
  else if constexpr (MODE == 1) { A = g_lnR; lda = 512; K = 512; B = pB; ldb = 512; C = g_kv; ldc = 1024; }
  else if constexpr (MODE == 2) { A = pA; lda = 512; K = 512; B = pB; ldb = 512; C = g_posp; ldc = 1024; }
  else if constexpr (MODE == 3) { bb = z >> 3; e = z & 7;
    A = g_q + (long)bb * 512 + e * 64; lda = 65536; K = 64;
    B = g_kv + (long)bb * 1024 + e * 64; ldb = 131072;
    C = g_A12 + (long)e * 8388608 + (long)bb * 256; ldc = 32768; }
  else if constexpr (MODE == 4) { e = z >> 8; bb = z & 255;
    A = g_q + (long)bb * 65536 + e * 64; lda = 512; K = 64;
    C = g_A12 + (long)e * 8388608 + (long)bb * 32768; ldc = 256; }
  else if constexpr (MODE == 5) { e = z >> 8; bb = z & 255;
    B = g_kv + (long)bb * 131072 + e * 64; ldb = 1024; K = 64;
    C = g_T3 + ((long)e * 256 + bb) * 32768; ldc = 128; }
  else if constexpr (MODE == 6) { bb = z >> 3; e = z & 7;
    A = g_A12 + (long)e * 8388608 + (long)bb * 256; lda = 32768; K = 256;
    B = g_kv + (long)bb * 1024 + 512 + e * 64; ldb = 131072;
    C = g_vo + (long)bb * 512 + e * 64; ldc = 65536; }
  else { A = g_vo; lda = 512; K = 512; B = pB; ldb = 512; C = pC; ldc = 512; }

  auto issue_tiles = [&](int k0, int stage) {
    float* dstA = Asm + stage * ASZ;
    float* dstB = Bsm + stage * BSZ;
#pragma unroll
    for (int it = 0; it < NA; ++it) {
      int t = (tid + it * 256) * 4;
      int i = t >> 4, kk = t & 15;
      float* d = &dstA[i * 20 + kk];
      if constexpr (MODE == 5) {
        int gi = pidx[(i0 + i) * 256 + bb];
        cpa16(d, g_posp + (long)gi * 1024 + e * 64 + k0 + kk, true);
      } else if constexpr (MODE == 2) {
        cpa16(d, A + (long)(i0 + i) * lda + k0 + kk, i0 + i < 511);
      } else {
        cpa16(d, A + (long)(i0 + i) * lda + k0 + kk, true);
      }
    }
#pragma unroll
    for (int it = 0; it < NB; ++it) {
      int t = (tid + it * 256) * 4;
      if constexpr (MODE == 6) {
        int kk = t / BN, j = t % BN;
        cpa16(&dstB[kk * 136 + j], B + (long)(k0 + kk) * ldb + j0 + j, true);
      } else if constexpr (MODE == 4) {
        int j = t >> 4, kk = t & 15;
        int gi = pidx[bb * 256 + j0 + j];
        cpa16(&dstB[j * 20 + kk], g_posp + (long)gi * 1024 + 512 + e * 64 + k0 + kk, true);
      } else {
        int j = t >> 4, kk = t & 15;
        cpa16(&dstB[j * 20 + kk], B + (long)(j0 + j) * ldb + k0 + kk, true);
      }
    }
  };

  float acc[MT][4][4];
#pragma unroll
  for (int m = 0; m < MT; ++m)
#pragma unroll
    for (int n = 0; n < 4; ++n)
#pragma unroll
      for (int r = 0; r < 4; ++r) acc[m][n][r] = 0.f;

  const int NIT = K / 16;
  issue_tiles(0, 0);  cpa_commit();
  issue_tiles(16, 1); cpa_commit();

  for (int itn = 0; itn < NIT; ++itn) {
    cpa_wait1();
    __syncthreads();
    int nxt = itn + 2;
    if (nxt < NIT) issue_tiles(nxt * 16, nxt % 3);
    cpa_commit();

    const int cur = itn % 3;
    const float* ap = Asm + cur * ASZ;
    const float* bp = Bsm + cur * BSZ;
#pragma unroll
    for (int ks = 0; ks < 2; ++ks) {
      const int kb = ks * 8;
      unsigned a[MT][4], b[4][2];
#pragma unroll
      for (int mt = 0; mt < MT; ++mt) {
        int r = wm0 + mt * 16 + gid;
        a[mt][0] = f2tf(ap[r * 20 + kb + tg]);
        a[mt][1] = f2tf(ap[(r + 8) * 20 + kb + tg]);
        a[mt][2] = f2tf(ap[r * 20 + kb + tg + 4]);
        a[mt][3] = f2tf(ap[(r + 8) * 20 + kb + tg + 4]);
      }
#pragma unroll
      for (int nt = 0; nt < 4; ++nt) {
        int cn = wn0 + nt * 8 + gid;
        if constexpr (MODE == 6) {
          b[nt][0] = f2tf(bp[(kb + tg) * 136 + cn]);
          b[nt][1] = f2tf(bp[(kb + tg + 4) * 136 + cn]);
        } else {
          b[nt][0] = f2tf(bp[cn * 20 + kb + tg]);
          b[nt][1] = f2tf(bp[cn * 20 + kb + tg + 4]);
        }
      }
#pragma unroll
      for (int mt = 0; mt < MT; ++mt)
#pragma unroll
        for (int nt = 0; nt < 4; ++nt) mma8(acc[mt][nt], a[mt], b[nt]);
    }
  }

  // ---- epilogue: each thread owns pairs (i, j), (i, j+1) and (i+8, ...) ----
#pragma unroll
  for (int mt = 0; mt < MT; ++mt) {
#pragma unroll
    for (int nt = 0; nt < 4; ++nt) {
      int j = j0 + wn0 + nt * 8 + 2 * tg;
#pragma unroll
      for (int h = 0; h < 2; ++h) {
        int i = i0 + wm0 + mt * 16 + gid + h * 8;
        if constexpr (MODE == 2) { if (i >= 511) continue; }
        float v0 = acc[mt][nt][h * 2 + 0];
        float v1 = acc[mt][nt][h * 2 + 1];
        float* cp = C + (long)i * ldc + j;
        if constexpr (MODE == 0) {
          float2 bv = *reinterpret_cast<const float2*>(pbias + j);
          v0 = (v0 + bv.x) * 0.125f; v1 = (v1 + bv.y) * 0.125f;
        } else if constexpr (MODE == 1) {
          float2 bv = *reinterpret_cast<const float2*>(pbias + j);
          v0 += bv.x; v1 += bv.y;
        } else if constexpr (MODE == 2) {
          float2 bv = *reinterpret_cast<const float2*>(pbias + j);
          float sc = (j < 512) ? 0.125f : 1.0f;
          v0 = (v0 + bv.x) * sc; v1 = (v1 + bv.y) * sc;
        } else if constexpr (MODE == 4) {
          float2 o = *reinterpret_cast<const float2*>(cp);
          v0 += o.x; v1 += o.y;
        } else if constexpr (MODE == 7) {
          float2 bv = *reinterpret_cast<const float2*>(pbias + j);
          float2 rv = *reinterpret_cast<const float2*>(presid + (long)i * 512 + j);
          v0 += bv.x + rv.x; v1 += bv.y + rv.y;
        }
        *reinterpret_cast<float2*>(cp) = make_float2(v0, v1);
      }
    }
  }
}

// ---------------- T3 transpose-add: A12[e][w][n][v] += T3[e][v][w][n] ----------------
__global__ void __launch_bounds__(256) t3_add_kernel() {
  int w = blockIdx.x, e = blockIdx.y;
  __shared__ float ts[32][129];
  long a12base = (long)e * 8388608 + (long)w * 32768;
  long t3base  = (long)e * 256 * 32768 + (long)w * 128;
  for (int v0 = 0; v0 < 256; v0 += 32) {
    for (int t = threadIdx.x; t < 32 * 128; t += 256) {
      int vj = t >> 7, n = t & 127;
      ts[vj][n] = g_T3[t3base + (long)(v0 + vj) * 32768 + n];
    }
    __syncthreads();
    for (int t = threadIdx.x; t < 32 * 128; t += 256) {
      int n = t >> 5, vj = t & 31;
      g_A12[a12base + n * 256 + v0 + vj] += ts[vj][n];
    }
    __syncthreads();
  }
}

// ------- Merged raw_attn + softmax, zero smem -------
__global__ void __launch_bounds__(256) raw_sm_kernel(float* __restrict__ out2) {
  const int w    = blockIdx.x;
  const int n    = blockIdx.y * 8 + (threadIdx.x >> 5);
  const int lane = threadIdx.x & 31;

  float raw0 = 0.f, raw1 = 0.f, raw2 = 0.f, raw3 = 0.f;
  float raw4 = 0.f, raw5 = 0.f, raw6 = 0.f, raw7 = 0.f;

#pragma unroll
  for (int e = 0; e < 8; ++e) {
    float* p = g_A12 + (long)e * 8388608 + (long)w * 32768 + n * 256;
    float4 a = ld4(p + lane * 4);
    float4 b = ld4(p + 128 + lane * 4);
    raw0 += a.x; raw1 += a.y; raw2 += a.z; raw3 += a.w;
    raw4 += b.x; raw5 += b.y; raw6 += b.z; raw7 += b.w;
    float mx = fmaxf(fmaxf(fmaxf(a.x, a.y), fmaxf(a.z, a.w)),
                     fmaxf(fmaxf(b.x, b.y), fmaxf(b.z, b.w)));
#pragma unroll
    for (int o = 16; o > 0; o >>= 1) mx = fmaxf(mx, __shfl_xor_sync(0xffffffffu, mx, o));
    a.x = __expf(a.x - mx); a.y = __expf(a.y - mx);
    a.z = __expf(a.z - mx); a.w = __expf(a.w - mx);
    b.x = __expf(b.x - mx); b.y = __expf(b.y - mx);
    b.z = __expf(b.z - mx); b.w = __expf(b.w - mx);
    float s = a.x + a.y + a.z + a.w + b.x + b.y + b.z + b.w;
#pragma unroll
    for (int o = 16; o > 0; o >>= 1) s += __shfl_xor_sync(0xffffffffu, s, o);
    float inv = 1.0f / s;
    a.x *= inv; a.y *= inv; a.z *= inv; a.w *= inv;
    b.x *= inv; b.y *= inv; b.z *= inv; b.w *= inv;
    *reinterpret_cast<float4*>(p + lane * 4) = a;
    *reinterpret_cast<float4*>(p + 128 + lane * 4) = b;
  }

  float* rp = out2 + ((long)n * 256 + w) * 256;
  *reinterpret_cast<float4*>(rp + lane * 4) = make_float4(raw0, raw1, raw2, raw3);
  *reinterpret_cast<float4*>(rp + 128 + lane * 4) = make_float4(raw4, raw5, raw6, raw7);
}

extern "C" void kernel_launch(void* const* d_in, const int* in_sizes, int n_in,
                              void* d_out, int out_size) {
  const float* feat_left   = (const float*)d_in[0];
  const float* feat_right  = (const float*)d_in[1];
  const float* pos         = (const float*)d_in[2];
  const int*   pos_indexes = (const int*)d_in[3];
  const float* ln_w        = (const float*)d_in[4];
  const float* ln_b        = (const float*)d_in[5];
  const float* in_proj_w   = (const float*)d_in[6];
  const float* in_proj_b   = (const float*)d_in[7];
  const float* out_w       = (const float*)d_in[8];
  const float* out_b       = (const float*)d_in[9];
  float* out = (float*)d_out;

  constexpr int S128 = 3 * (128 * 20 + 128 * 20) * 4;   // 61440
  constexpr int S64  = 3 * (64 * 20 + 64 * 20) * 4;     // 30720
  constexpr int S6   = 3 * (128 * 20 + 16 * 136) * 4;   // 56832
  cudaFuncSetAttribute(gemm_k<0, 128, 128>, cudaFuncAttributeMaxDynamicSharedMemorySize, S128);
  cudaFuncSetAttribute(gemm_k<1, 128, 128>, cudaFuncAttributeMaxDynamicSharedMemorySize, S128);
  cudaFuncSetAttribute(gemm_k<3, 128, 128>, cudaFuncAttributeMaxDynamicSharedMemorySize, S128);
  cudaFuncSetAttribute(gemm_k<4, 128, 128>, cudaFuncAttributeMaxDynamicSharedMemorySize, S128);
  cudaFuncSetAttribute(gemm_k<5, 128, 128>, cudaFuncAttributeMaxDynamicSharedMemorySize, S128);
  cudaFuncSetAttribute(gemm_k<7, 128, 128>, cudaFuncAttributeMaxDynamicSharedMemorySize, S128);
  cudaFuncSetAttribute(gemm_k<6, 128, 64>,  cudaFuncAttributeMaxDynamicSharedMemorySize, S6);

  ln_kernel<<<65536, 128>>>(feat_left, feat_right, ln_w, ln_b);

  gemm_k<0, 128, 128><<<dim3(4, 256, 1), 256, S128>>>(
      nullptr, in_proj_w, in_proj_b, nullptr, nullptr, nullptr);
  gemm_k<1, 128, 128><<<dim3(8, 256, 1), 256, S128>>>(
      nullptr, in_proj_w + 512 * 512, in_proj_b + 512, nullptr, nullptr, nullptr);
  gemm_k<2, 64, 64><<<dim3(16, 8, 1), 256, S64>>>(
      pos, in_proj_w, in_proj_b, nullptr, nullptr, nullptr);

  gemm_k<3, 128, 128><<<dim3(2, 2, 1024), 256, S128>>>(
      nullptr, nullptr, nullptr, nullptr, nullptr, nullptr);
  gemm_k<4, 128, 128><<<dim3(2, 1, 2048), 256, S128>>>(
      nullptr, nullptr, nullptr, nullptr, pos_indexes, nullptr);
  gemm_k<5, 128, 128><<<dim3(1, 2, 2048), 256, S128>>>(
      nullptr, nullptr, nullptr, nullptr, pos_indexes, nullptr);

  t3_add_kernel<<<dim3(256, 8), 256>>>();
  raw_sm_kernel<<<dim3(256, 16), 256>>>(out + 16777216);

  gemm_k<6, 128, 64><<<dim3(1, 2, 1024), 256, S6>>>(
      nullptr, nullptr, nullptr, nullptr, nullptr, nullptr);
  gemm_k<7, 128, 128><<<dim3(4, 256, 1), 256, S128>>>(
      nullptr, out_w, out_b, feat_left, nullptr, out);
}